// round 16
// baseline (speedup 1.0000x reference)
#include <cuda_runtime.h>
#include <cstdint>

#define VOCAB 21128
#define EMB   768
#define HID   256
#define NTAGS 8
#define BATCH 64
#define SEQ   512
#define NTOK  (BATCH * SEQ)
#define NCORP 10
#define NCH   16
#define CL    32

#define ZROWS  21248                  // vocab padded to 332*64
#define QS     1024.0f
#define IQS2   9.5367431640625e-07f   // 1 / (1024*1024)

// ---------------- scratch (device globals; no allocs allowed) ----------------
__device__ float g_logits[NTOK * NTAGS];
__device__ float g_ctr10[NCORP * HID];
__device__ __align__(16) unsigned g_fc1i8[24 * 2048];  // fc1_w s8*1024, [ks][n][8w]
__device__ __align__(16) unsigned g_Zh[ZROWS * HID / 2]; // Z in bf16x2 (8.5 MB)
__device__ int   g_flags[VOCAB];
__device__ int   g_slot[VOCAB];
__device__ int   g_wlist[ZROWS];
__device__ int   g_count;

// ---------------------------------------------------------------------------
__device__ __forceinline__ unsigned pack_s8x4(int x0, int x1, int x2, int x3) {
    unsigned t, r, z = 0;
    asm("cvt.pack.sat.s8.s32.b32 %0, %1, %2, %3;" : "=r"(t) : "r"(x3), "r"(x2), "r"(z));
    asm("cvt.pack.sat.s8.s32.b32 %0, %1, %2, %3;" : "=r"(r) : "r"(x1), "r"(x0), "r"(t));
    return r;
}
__device__ __forceinline__ int q8(float x) { return __float2int_rn(x * QS); }
// pack 2 fp32 -> bf16x2 (lo = x, hi = y)
__device__ __forceinline__ unsigned pack_bf(float x, float y) {
    unsigned u;
    asm("cvt.rn.bf16x2.f32 %0, %1, %2;" : "=r"(u) : "f"(y), "f"(x));
    return u;
}
__device__ __forceinline__ float bf_lo(unsigned w) { return __uint_as_float(w << 16); }
__device__ __forceinline__ float bf_hi(unsigned w) { return __uint_as_float(w & 0xffff0000u); }

__device__ __forceinline__ void imma32(int* c, const unsigned* a, unsigned b0, unsigned b1) {
    asm volatile(
        "mma.sync.aligned.m16n8k32.row.col.s32.s8.s8.s32 "
        "{%0,%1,%2,%3},{%4,%5,%6,%7},{%8,%9},{%0,%1,%2,%3};"
        : "+r"(c[0]), "+r"(c[1]), "+r"(c[2]), "+r"(c[3])
        : "r"(a[0]), "r"(a[1]), "r"(a[2]), "r"(a[3]), "r"(b0), "r"(b1));
}

// ---------------------------------------------------------------------------
// prep_all: fused weight-quant + domain-ctr + metadata zeroing.
// ---------------------------------------------------------------------------
__global__ __launch_bounds__(256) void prep_all(
    const float* __restrict__ fc1_w,
    const float* __restrict__ dom_w,
    const float* __restrict__ fc1_b) {

    __shared__ float sDom[HID];
    const int bx = blockIdx.x, tid = threadIdx.x;

    if (bx < 96) {
        int id = bx * 256 + tid;
        int ks = id >> 10, rem = id & 1023;
        int n = rem >> 2, q = rem & 3;
        const float* src = fc1_w + n * (HID + EMB) + ks * 32 + q * 8;
        float4 v0 = *(const float4*)(src);
        float4 v1 = *(const float4*)(src + 4);
        uint2 o;
        o.x = pack_s8x4(q8(v0.x), q8(v0.y), q8(v0.z), q8(v0.w));
        o.y = pack_s8x4(q8(v1.x), q8(v1.y), q8(v1.z), q8(v1.w));
        ((uint2*)g_fc1i8)[ks * 1024 + n * 4 + q] = o;
    } else if (bx < 106) {
        const int c = bx - 96;
        sDom[tid] = dom_w[c * HID + tid];
        __syncthreads();
        const int w = tid >> 5, lane = tid & 31;
        for (int n = w; n < HID; n += 8) {
            const float* row = fc1_w + n * (HID + EMB) + EMB;
            float4 x0 = *(const float4*)(row + lane * 4);
            float4 x1 = *(const float4*)(row + 128 + lane * 4);
            float4 d0 = *(const float4*)(sDom + lane * 4);
            float4 d1 = *(const float4*)(sDom + 128 + lane * 4);
            float acc = x0.x * d0.x + x0.y * d0.y + x0.z * d0.z + x0.w * d0.w
                      + x1.x * d1.x + x1.y * d1.y + x1.z * d1.z + x1.w * d1.w;
#pragma unroll
            for (int off = 16; off > 0; off >>= 1)
                acc += __shfl_down_sync(0xffffffffu, acc, off);
            if (lane == 0) g_ctr10[c * HID + n] = acc + fc1_b[n];
        }
    } else {
        int i = (bx - 106) * 256 + tid;
        if (i < VOCAB) g_flags[i] = 0;
        if (i < ZROWS) g_wlist[i] = 0;
        if (i == 0) g_count = 0;
    }
}

// ---------------------------------------------------------------------------
// flag_compact: token-driven dedup + warp-aggregated slot assignment.
// ---------------------------------------------------------------------------
__global__ __launch_bounds__(512) void flag_compact(const int* __restrict__ words) {
    const int tid = threadIdx.x, lane = tid & 31;
    const int w = words[blockIdx.x * 512 + tid];
    const int isnew = (atomicExch(&g_flags[w], 1) == 0);
    unsigned mask = __ballot_sync(0xffffffffu, isnew);
    int n = __popc(mask);
    int base = 0;
    if (lane == 0 && n) base = atomicAdd(&g_count, n);
    base = __shfl_sync(0xffffffffu, base, 0);
    if (isnew) {
        int slot = base + __popc(mask & ((1u << lane) - 1));
        g_slot[w] = slot;
        g_wlist[slot] = w;
    }
}

// ---------------------------------------------------------------------------
// gemm_z: Zh[slot, 256] = bf16(embed[wlist[slot]] @ W1emb^T) via int8 IMMA.
// ---------------------------------------------------------------------------
#define GST    12
#define GSTAGE 3840
#define GBOFF  768

__global__ __launch_bounds__(256, 2) void gemm_z(const float* __restrict__ embed_w) {
    __shared__ unsigned S[2 * GSTAGE];

    const int m0 = blockIdx.x * 64;
    const int padded = (g_count + 63) & ~63;
    if (m0 >= padded) return;

    const int tid  = threadIdx.x;
    const int warp = tid >> 5, lane = tid & 31;
    const int wm = warp >> 2, wn = warp & 3;
    const int gr = lane >> 2, tc = lane & 3;

    const int aR = tid >> 2, aQ = tid & 3;
    const float* aSrc = embed_w + (long)__ldg(g_wlist + m0 + aR) * EMB + aQ * 8;
    const uint4* bSrc = (const uint4*)g_fc1i8 + tid * 2;

    const int aDst = aR * GST + aQ * 2;
    const int bDst = GBOFF + tid * GST;

    int acc[2][8][4];
#pragma unroll
    for (int mi = 0; mi < 2; mi++)
#pragma unroll
        for (int nj = 0; nj < 8; nj++)
#pragma unroll
            for (int q = 0; q < 4; q++) acc[mi][nj][q] = 0;

    float4 aV0 = *(const float4*)(aSrc);
    float4 aV1 = *(const float4*)(aSrc + 4);
    uint4  bV0 = *(bSrc);
    uint4  bV1 = *(bSrc + 1);
    {
        uint2 o;
        o.x = pack_s8x4(q8(aV0.x), q8(aV0.y), q8(aV0.z), q8(aV0.w));
        o.y = pack_s8x4(q8(aV1.x), q8(aV1.y), q8(aV1.z), q8(aV1.w));
        *(uint2*)(S + aDst) = o;
        *(uint4*)(S + bDst) = bV0;
        *(uint4*)(S + bDst + 4) = bV1;
    }
    __syncthreads();

    const int r0a = wm * 32 + gr;
    const int n0  = wn * 64 + gr;

#pragma unroll 2
    for (int it = 0; it < 24; ++it) {
        unsigned* cur = S + (it & 1) * GSTAGE;

        if (it + 1 < 24) {
            const float* ap = aSrc + (it + 1) * 32;
            aV0 = *(const float4*)(ap);
            aV1 = *(const float4*)(ap + 4);
            const uint4* bp = bSrc + (it + 1) * 512;
            bV0 = *(bp);
            bV1 = *(bp + 1);
        }

        unsigned a[2][4];
#pragma unroll
        for (int mi = 0; mi < 2; mi++) {
            int r0 = r0a + mi * 16;
            a[mi][0] = cur[r0 * GST + tc];
            a[mi][1] = cur[(r0 + 8) * GST + tc];
            a[mi][2] = cur[r0 * GST + tc + 4];
            a[mi][3] = cur[(r0 + 8) * GST + tc + 4];
        }
#pragma unroll
        for (int nj = 0; nj < 8; nj++) {
            int n = n0 + nj * 8;
            unsigned b0 = cur[GBOFF + n * GST + tc];
            unsigned b1 = cur[GBOFF + n * GST + tc + 4];
            imma32(acc[0][nj], a[0], b0, b1);
            imma32(acc[1][nj], a[1], b0, b1);
        }

        if (it + 1 < 24) {
            unsigned* nxt = S + ((it + 1) & 1) * GSTAGE;
            uint2 o;
            o.x = pack_s8x4(q8(aV0.x), q8(aV0.y), q8(aV0.z), q8(aV0.w));
            o.y = pack_s8x4(q8(aV1.x), q8(aV1.y), q8(aV1.z), q8(aV1.w));
            *(uint2*)(nxt + aDst) = o;
            *(uint4*)(nxt + bDst) = bV0;
            *(uint4*)(nxt + bDst + 4) = bV1;
        }
        __syncthreads();
    }

    // epilogue: Zh = bf16(acc * 2^-20); col pair -> one bf16x2 word
#pragma unroll
    for (int mi = 0; mi < 2; mi++)
#pragma unroll
        for (int half = 0; half < 2; half++) {
            int row = wm * 32 + mi * 16 + half * 8 + gr;
#pragma unroll
            for (int nj = 0; nj < 8; nj++) {
                int col = wn * 64 + nj * 8 + tc * 2;
                float zx = (float)acc[mi][nj][half * 2 + 0] * IQS2;
                float zy = (float)acc[mi][nj][half * 2 + 1] * IQS2;
                g_Zh[(long)(m0 + row) * (HID / 2) + (col >> 1)] = pack_bf(zx, zy);
            }
        }
}

// ---------------------------------------------------------------------------
// tok_kernel v5: warp-per-token, 4 tokens/warp, bf16 Z (one uint4 per token),
// front-batched. Tag-splitting butterfly + 6-shfl softmax.
// grid 1024, block 256.
// ---------------------------------------------------------------------------
__global__ __launch_bounds__(256, 2) void tok_kernel(
    const int* __restrict__ words,
    const int* __restrict__ corpus,
    const float* __restrict__ fc2_w,
    const float* __restrict__ fc2_b) {

    const int tid = threadIdx.x, wid = tid >> 5, lane = tid & 31;
    const int gw = blockIdx.x * 8 + wid;
    const int tok0 = gw * 4;
    const int b = tok0 >> 9;
    const int cix = __ldg(corpus + b);
    const unsigned FULL = 0xffffffffu;

    float d[8];
    {
        float4 u0 = __ldg((const float4*)(g_ctr10 + cix * HID + lane * 8));
        float4 u1 = __ldg((const float4*)(g_ctr10 + cix * HID + lane * 8 + 4));
        d[0] = u0.x; d[1] = u0.y; d[2] = u0.z; d[3] = u0.w;
        d[4] = u1.x; d[5] = u1.y; d[6] = u1.z; d[7] = u1.w;
    }
    float w2[NTAGS][8];
#pragma unroll
    for (int t = 0; t < NTAGS; t++) {
        float4 u0 = __ldg((const float4*)(fc2_w + t * HID + lane * 8));
        float4 u1 = __ldg((const float4*)(fc2_w + t * HID + lane * 8 + 4));
        w2[t][0] = u0.x; w2[t][1] = u0.y; w2[t][2] = u0.z; w2[t][3] = u0.w;
        w2[t][4] = u1.x; w2[t][5] = u1.y; w2[t][6] = u1.z; w2[t][7] = u1.w;
    }
    const int tag = ((lane >> 4) & 1) * 4 + ((lane >> 3) & 1) * 2 + ((lane >> 2) & 1);
    const float fbt = __ldg(fc2_b + tag);

    int sl[4];
#pragma unroll
    for (int k = 0; k < 4; k++)
        sl[k] = __ldg(g_slot + __ldg(words + tok0 + k));
    uint4 zz[4];
#pragma unroll
    for (int k = 0; k < 4; k++)
        zz[k] = __ldg((const uint4*)(g_Zh + (long)sl[k] * (HID / 2) + lane * 4));

#pragma unroll
    for (int k = 0; k < 4; k++) {
        float h[8];
        h[0] = fmaxf(bf_lo(zz[k].x) + d[0], 0.f); h[1] = fmaxf(bf_hi(zz[k].x) + d[1], 0.f);
        h[2] = fmaxf(bf_lo(zz[k].y) + d[2], 0.f); h[3] = fmaxf(bf_hi(zz[k].y) + d[3], 0.f);
        h[4] = fmaxf(bf_lo(zz[k].z) + d[4], 0.f); h[5] = fmaxf(bf_hi(zz[k].z) + d[5], 0.f);
        h[6] = fmaxf(bf_lo(zz[k].w) + d[6], 0.f); h[7] = fmaxf(bf_hi(zz[k].w) + d[7], 0.f);

        float p[NTAGS];
#pragma unroll
        for (int t = 0; t < NTAGS; t++) {
            float s = 0.f;
#pragma unroll
            for (int q = 0; q < 8; q++) s = fmaf(h[q], w2[t][q], s);
            p[t] = s;
        }

        // tag-splitting butterfly: 9 shfls
#pragma unroll
        for (int i = 0; i < 4; i++) {
            float send = (lane & 16) ? p[i] : p[i + 4];
            float r = __shfl_xor_sync(FULL, send, 16);
            p[i] = ((lane & 16) ? p[i + 4] : p[i]) + r;
        }
#pragma unroll
        for (int i = 0; i < 2; i++) {
            float send = (lane & 8) ? p[i] : p[i + 2];
            float r = __shfl_xor_sync(FULL, send, 8);
            p[i] = ((lane & 8) ? p[i + 2] : p[i]) + r;
        }
        float v;
        {
            float send = (lane & 4) ? p[0] : p[1];
            float r = __shfl_xor_sync(FULL, send, 4);
            v = ((lane & 4) ? p[1] : p[0]) + r;
        }
        v += __shfl_xor_sync(FULL, v, 1);
        v += __shfl_xor_sync(FULL, v, 2);
        v += fbt;

        // softmax over tags (lanes differing in bits 2,3,4)
        float mx = v;
        mx = fmaxf(mx, __shfl_xor_sync(FULL, mx, 4));
        mx = fmaxf(mx, __shfl_xor_sync(FULL, mx, 8));
        mx = fmaxf(mx, __shfl_xor_sync(FULL, mx, 16));
        float sm = __expf(v - mx);
        sm += __shfl_xor_sync(FULL, sm, 4);
        sm += __shfl_xor_sync(FULL, sm, 8);
        sm += __shfl_xor_sync(FULL, sm, 16);
        float lse = mx + __logf(sm);

        if ((lane & 3) == 0)
            g_logits[(long)(tok0 + k) * NTAGS + tag] = v - lse;
    }
}

// ---------------------------------------------------------------------------
// crf_all (MERGED): grid 64, block 1024. Per batch elem:
//   Phase 1: 16 chunks x 32-step operator scans (logits+words staged in smem)
//   Phase 2: combine 16 matrices -> norm (threads 0..7)
//   Phase 3: gold path score (threads 0..511) + final loss
// ---------------------------------------------------------------------------
__global__ __launch_bounds__(1024) void crf_all(
    const int* __restrict__ words,
    const int* __restrict__ target,
    const float* __restrict__ trans,
    const float* __restrict__ start_s,
    const float* __restrict__ end_s,
    float* __restrict__ out) {

    __shared__ float sL[SEQ * NTAGS];     // 16 KB
    __shared__ int   sW[SEQ];             // 2 KB
    __shared__ float sM[NCH * 64];        // 4 KB
    __shared__ float sRed[16];
    __shared__ int   sRedI[16];
    __shared__ float sNorm;

    const int b = blockIdx.x, tid = threadIdx.x;
    const int chunk = tid >> 6, l64 = tid & 63;
    const int lane = tid & 31, j = tid & 7, rowBase = lane & ~7;

    *(float4*)&sL[tid * 4] = *(const float4*)(g_logits + (long)b * SEQ * NTAGS + tid * 4);
    if (tid < SEQ) sW[tid] = words[b * SEQ + tid];

    float tcol[8];
#pragma unroll
    for (int k = 0; k < 8; k++) tcol[k] = __ldg(trans + k * NTAGS + j);
    __syncthreads();

    // Phase 1: chunk operator scan
    float M = ((l64 >> 3) == j) ? 0.f : -1e30f;
#pragma unroll 4
    for (int si = 0; si < CL; si++) {
        const int s = chunk * CL + si;
        float emit = sL[s * NTAGS + j];
        int live = (sW[s] != 0) & (s > 0);
        float v[8];
#pragma unroll
        for (int k = 0; k < 8; k++)
            v[k] = __shfl_sync(0xffffffffu, M, rowBase + k) + tcol[k];
        float m01 = fmaxf(v[0], v[1]), m23 = fmaxf(v[2], v[3]);
        float m45 = fmaxf(v[4], v[5]), m67 = fmaxf(v[6], v[7]);
        float mx  = fmaxf(fmaxf(m01, m23), fmaxf(m45, m67));
        float s0 = __expf(v[0] - mx) + __expf(v[1] - mx);
        float s1 = __expf(v[2] - mx) + __expf(v[3] - mx);
        float s2 = __expf(v[4] - mx) + __expf(v[5] - mx);
        float s3 = __expf(v[6] - mx) + __expf(v[7] - mx);
        float nv = mx + __logf((s0 + s1) + (s2 + s3)) + emit;
        M = live ? nv : M;
    }
    sM[chunk * 64 + l64] = M;
    __syncthreads();

    // Phase 2: combine + norm (warp 0, threads 0..7)
    if (tid < 8) {
        float alpha = sL[tid] + __ldg(start_s + tid);
#pragma unroll
        for (int c = 0; c < NCH; c++) {
            float v[8];
#pragma unroll
            for (int k = 0; k < 8; k++)
                v[k] = __shfl_sync(0xffu, alpha, k) + sM[c * 64 + k * 8 + tid];
            float m01 = fmaxf(v[0], v[1]), m23 = fmaxf(v[2], v[3]);
            float m45 = fmaxf(v[4], v[5]), m67 = fmaxf(v[6], v[7]);
            float mx  = fmaxf(fmaxf(m01, m23), fmaxf(m45, m67));
            float sm = __expf(v[0] - mx) + __expf(v[1] - mx) + __expf(v[2] - mx)
                     + __expf(v[3] - mx) + __expf(v[4] - mx) + __expf(v[5] - mx)
                     + __expf(v[6] - mx) + __expf(v[7] - mx);
            alpha = mx + __logf(sm);
        }
        float v = alpha + __ldg(end_s + tid);
        float mx = v;
        mx = fmaxf(mx, __shfl_xor_sync(0xffu, mx, 1));
        mx = fmaxf(mx, __shfl_xor_sync(0xffu, mx, 2));
        mx = fmaxf(mx, __shfl_xor_sync(0xffu, mx, 4));
        float sm = __expf(v - mx);
        sm += __shfl_xor_sync(0xffu, sm, 1);
        sm += __shfl_xor_sync(0xffu, sm, 2);
        sm += __shfl_xor_sync(0xffu, sm, 4);
        if (tid == 0) sNorm = mx + __logf(sm);
    }

    // Phase 3: gold path score (threads 0..511, one per position)
    if (tid < SEQ) {
        const int s = tid;
        int m = (sW[s] != 0);
        int t = __ldg(target + b * SEQ + s);
        float e  = m ? sL[s * NTAGS + t] : 0.f;
        float tr = (m && s > 0) ? __ldg(trans + __ldg(target + b * SEQ + s - 1) * NTAGS + t) : 0.f;
        float val = e + tr;
        int cnt = m;
#pragma unroll
        for (int off = 16; off > 0; off >>= 1) {
            val += __shfl_down_sync(0xffffffffu, val, off);
            cnt += __shfl_down_sync(0xffffffffu, cnt, off);
        }
        if (lane == 0) { sRed[tid >> 5] = val; sRedI[tid >> 5] = cnt; }
    }
    __syncthreads();
    if (tid == 0) {
        float sum = 0.f; int c = 0;
#pragma unroll
        for (int w = 0; w < 16; w++) { sum += sRed[w]; c += sRedI[w]; }
        int last = c - 1;
        const int* tg = target + b * SEQ;
        float score = sum + __ldg(start_s + __ldg(tg)) + __ldg(end_s + __ldg(tg + last));
        out[b] = sNorm - score;
    }
}

// ---------------------------------------------------------------------------
extern "C" void kernel_launch(void* const* d_in, const int* in_sizes, int n_in,
                              void* d_out, int out_size) {
    const int*   words   = (const int*)  d_in[0];
    const int*   target  = (const int*)  d_in[1];
    const int*   corpus  = (const int*)  d_in[2];
    const float* embed_w = (const float*)d_in[3];
    const float* dom_w   = (const float*)d_in[4];
    const float* fc1_w   = (const float*)d_in[5];
    const float* fc1_b   = (const float*)d_in[6];
    const float* fc2_w   = (const float*)d_in[7];
    const float* fc2_b   = (const float*)d_in[8];
    const float* trans   = (const float*)d_in[9];
    const float* start_s = (const float*)d_in[10];
    const float* end_s   = (const float*)d_in[11];
    float* out = (float*)d_out;

    prep_all<<<190, 256>>>(fc1_w, dom_w, fc1_b);
    flag_compact<<<64, 512>>>(words);
    gemm_z<<<332, 256>>>(embed_w);
    tok_kernel<<<1024, 256>>>(words, corpus, fc2_w, fc2_b);
    crf_all<<<BATCH, 1024>>>(words, target, trans, start_s, end_s, out);
}

// round 17
// speedup vs baseline: 1.0996x; 1.0996x over previous
#include <cuda_runtime.h>
#include <cstdint>

#define VOCAB 21128
#define EMB   768
#define HID   256
#define NTAGS 8
#define BATCH 64
#define SEQ   512
#define NTOK  (BATCH * SEQ)
#define NCORP 10
#define NCHUNK 32
#define CLEN   16

#define ZROWS  21248                  // vocab padded to 332*64
#define QS     1024.0f
#define IQS2   9.5367431640625e-07f   // 1 / (1024*1024)

// ---------------- scratch (device globals; no allocs allowed) ----------------
__device__ float g_logits[NTOK * NTAGS];
__device__ float g_ctr10[NCORP * HID];
__device__ __align__(16) unsigned g_fc1i8[24 * 2048];    // fc1_w s8*1024
__device__ __align__(16) unsigned g_Zh[ZROWS * HID / 2]; // Z in bf16x2 (8.5 MB)
__device__ float g_crfM[BATCH * NCHUNK * 64];
__device__ int   g_flags[VOCAB];
__device__ int   g_slot[VOCAB];
__device__ int   g_wlist[ZROWS];
__device__ int   g_count;

// ---------------------------------------------------------------------------
__device__ __forceinline__ unsigned pack_s8x4(int x0, int x1, int x2, int x3) {
    unsigned t, r, z = 0;
    asm("cvt.pack.sat.s8.s32.b32 %0, %1, %2, %3;" : "=r"(t) : "r"(x3), "r"(x2), "r"(z));
    asm("cvt.pack.sat.s8.s32.b32 %0, %1, %2, %3;" : "=r"(r) : "r"(x1), "r"(x0), "r"(t));
    return r;
}
__device__ __forceinline__ int q8(float x) { return __float2int_rn(x * QS); }
__device__ __forceinline__ unsigned pack_bf(float x, float y) {
    unsigned u;
    asm("cvt.rn.bf16x2.f32 %0, %1, %2;" : "=r"(u) : "f"(y), "f"(x));
    return u;
}
__device__ __forceinline__ float bf_lo(unsigned w) { return __uint_as_float(w << 16); }
__device__ __forceinline__ float bf_hi(unsigned w) { return __uint_as_float(w & 0xffff0000u); }

__device__ __forceinline__ void imma32(int* c, const unsigned* a, unsigned b0, unsigned b1) {
    asm volatile(
        "mma.sync.aligned.m16n8k32.row.col.s32.s8.s8.s32 "
        "{%0,%1,%2,%3},{%4,%5,%6,%7},{%8,%9},{%0,%1,%2,%3};"
        : "+r"(c[0]), "+r"(c[1]), "+r"(c[2]), "+r"(c[3])
        : "r"(a[0]), "r"(a[1]), "r"(a[2]), "r"(a[3]), "r"(b0), "r"(b1));
}

// ---------------------------------------------------------------------------
// prep_all: fused weight-quant + domain-ctr + metadata zeroing.
// ---------------------------------------------------------------------------
__global__ __launch_bounds__(256) void prep_all(
    const float* __restrict__ fc1_w,
    const float* __restrict__ dom_w,
    const float* __restrict__ fc1_b) {

    __shared__ float sDom[HID];
    const int bx = blockIdx.x, tid = threadIdx.x;

    if (bx < 96) {
        int id = bx * 256 + tid;
        int ks = id >> 10, rem = id & 1023;
        int n = rem >> 2, q = rem & 3;
        const float* src = fc1_w + n * (HID + EMB) + ks * 32 + q * 8;
        float4 v0 = *(const float4*)(src);
        float4 v1 = *(const float4*)(src + 4);
        uint2 o;
        o.x = pack_s8x4(q8(v0.x), q8(v0.y), q8(v0.z), q8(v0.w));
        o.y = pack_s8x4(q8(v1.x), q8(v1.y), q8(v1.z), q8(v1.w));
        ((uint2*)g_fc1i8)[ks * 1024 + n * 4 + q] = o;
    } else if (bx < 106) {
        const int c = bx - 96;
        sDom[tid] = dom_w[c * HID + tid];
        __syncthreads();
        const int w = tid >> 5, lane = tid & 31;
        for (int n = w; n < HID; n += 8) {
            const float* row = fc1_w + n * (HID + EMB) + EMB;
            float4 x0 = *(const float4*)(row + lane * 4);
            float4 x1 = *(const float4*)(row + 128 + lane * 4);
            float4 d0 = *(const float4*)(sDom + lane * 4);
            float4 d1 = *(const float4*)(sDom + 128 + lane * 4);
            float acc = x0.x * d0.x + x0.y * d0.y + x0.z * d0.z + x0.w * d0.w
                      + x1.x * d1.x + x1.y * d1.y + x1.z * d1.z + x1.w * d1.w;
#pragma unroll
            for (int off = 16; off > 0; off >>= 1)
                acc += __shfl_down_sync(0xffffffffu, acc, off);
            if (lane == 0) g_ctr10[c * HID + n] = acc + fc1_b[n];
        }
    } else {
        int i = (bx - 106) * 256 + tid;
        if (i < VOCAB) g_flags[i] = 0;
        if (i < ZROWS) g_wlist[i] = 0;
        if (i == 0) g_count = 0;
    }
}

// ---------------------------------------------------------------------------
// flag_compact: token-driven dedup + warp-aggregated slot assignment.
// ---------------------------------------------------------------------------
__global__ __launch_bounds__(512) void flag_compact(const int* __restrict__ words) {
    const int tid = threadIdx.x, lane = tid & 31;
    const int w = words[blockIdx.x * 512 + tid];
    const int isnew = (atomicExch(&g_flags[w], 1) == 0);
    unsigned mask = __ballot_sync(0xffffffffu, isnew);
    int n = __popc(mask);
    int base = 0;
    if (lane == 0 && n) base = atomicAdd(&g_count, n);
    base = __shfl_sync(0xffffffffu, base, 0);
    if (isnew) {
        int slot = base + __popc(mask & ((1u << lane) - 1));
        g_slot[w] = slot;
        g_wlist[slot] = w;
    }
}

// ---------------------------------------------------------------------------
// gemm_z: Zh[slot, 256] = bf16(embed[wlist[slot]] @ W1emb^T) via int8 IMMA.
// ---------------------------------------------------------------------------
#define GST    12
#define GSTAGE 3840
#define GBOFF  768

__global__ __launch_bounds__(256, 2) void gemm_z(const float* __restrict__ embed_w) {
    __shared__ unsigned S[2 * GSTAGE];

    const int m0 = blockIdx.x * 64;
    const int padded = (g_count + 63) & ~63;
    if (m0 >= padded) return;

    const int tid  = threadIdx.x;
    const int warp = tid >> 5, lane = tid & 31;
    const int wm = warp >> 2, wn = warp & 3;
    const int gr = lane >> 2, tc = lane & 3;

    const int aR = tid >> 2, aQ = tid & 3;
    const float* aSrc = embed_w + (long)__ldg(g_wlist + m0 + aR) * EMB + aQ * 8;
    const uint4* bSrc = (const uint4*)g_fc1i8 + tid * 2;

    const int aDst = aR * GST + aQ * 2;
    const int bDst = GBOFF + tid * GST;

    int acc[2][8][4];
#pragma unroll
    for (int mi = 0; mi < 2; mi++)
#pragma unroll
        for (int nj = 0; nj < 8; nj++)
#pragma unroll
            for (int q = 0; q < 4; q++) acc[mi][nj][q] = 0;

    float4 aV0 = *(const float4*)(aSrc);
    float4 aV1 = *(const float4*)(aSrc + 4);
    uint4  bV0 = *(bSrc);
    uint4  bV1 = *(bSrc + 1);
    {
        uint2 o;
        o.x = pack_s8x4(q8(aV0.x), q8(aV0.y), q8(aV0.z), q8(aV0.w));
        o.y = pack_s8x4(q8(aV1.x), q8(aV1.y), q8(aV1.z), q8(aV1.w));
        *(uint2*)(S + aDst) = o;
        *(uint4*)(S + bDst) = bV0;
        *(uint4*)(S + bDst + 4) = bV1;
    }
    __syncthreads();

    const int r0a = wm * 32 + gr;
    const int n0  = wn * 64 + gr;

#pragma unroll 2
    for (int it = 0; it < 24; ++it) {
        unsigned* cur = S + (it & 1) * GSTAGE;

        if (it + 1 < 24) {
            const float* ap = aSrc + (it + 1) * 32;
            aV0 = *(const float4*)(ap);
            aV1 = *(const float4*)(ap + 4);
            const uint4* bp = bSrc + (it + 1) * 512;
            bV0 = *(bp);
            bV1 = *(bp + 1);
        }

        unsigned a[2][4];
#pragma unroll
        for (int mi = 0; mi < 2; mi++) {
            int r0 = r0a + mi * 16;
            a[mi][0] = cur[r0 * GST + tc];
            a[mi][1] = cur[(r0 + 8) * GST + tc];
            a[mi][2] = cur[r0 * GST + tc + 4];
            a[mi][3] = cur[(r0 + 8) * GST + tc + 4];
        }
#pragma unroll
        for (int nj = 0; nj < 8; nj++) {
            int n = n0 + nj * 8;
            unsigned b0 = cur[GBOFF + n * GST + tc];
            unsigned b1 = cur[GBOFF + n * GST + tc + 4];
            imma32(acc[0][nj], a[0], b0, b1);
            imma32(acc[1][nj], a[1], b0, b1);
        }

        if (it + 1 < 24) {
            unsigned* nxt = S + ((it + 1) & 1) * GSTAGE;
            uint2 o;
            o.x = pack_s8x4(q8(aV0.x), q8(aV0.y), q8(aV0.z), q8(aV0.w));
            o.y = pack_s8x4(q8(aV1.x), q8(aV1.y), q8(aV1.z), q8(aV1.w));
            *(uint2*)(nxt + aDst) = o;
            *(uint4*)(nxt + bDst) = bV0;
            *(uint4*)(nxt + bDst + 4) = bV1;
        }
        __syncthreads();
    }

    // epilogue: Zh = bf16(acc * 2^-20)
#pragma unroll
    for (int mi = 0; mi < 2; mi++)
#pragma unroll
        for (int half = 0; half < 2; half++) {
            int row = wm * 32 + mi * 16 + half * 8 + gr;
#pragma unroll
            for (int nj = 0; nj < 8; nj++) {
                int col = wn * 64 + nj * 8 + tc * 2;
                float zx = (float)acc[mi][nj][half * 2 + 0] * IQS2;
                float zy = (float)acc[mi][nj][half * 2 + 1] * IQS2;
                g_Zh[(long)(m0 + row) * (HID / 2) + (col >> 1)] = pack_bf(zx, zy);
            }
        }
}

// ---------------------------------------------------------------------------
// tok_kernel v6: warp-per-token, 8 tokens/warp, bf16 Z (one uint4/token),
// ALL loads front-batched (MLP=8/warp). Tag-split butterfly + 6-shfl softmax.
// grid 512, block 256 (4096 warps x 8 tokens).
// ---------------------------------------------------------------------------
__global__ __launch_bounds__(256, 2) void tok_kernel(
    const int* __restrict__ words,
    const int* __restrict__ corpus,
    const float* __restrict__ fc2_w,
    const float* __restrict__ fc2_b) {

    const int tid = threadIdx.x, wid = tid >> 5, lane = tid & 31;
    const int gw = blockIdx.x * 8 + wid;          // 0..4095
    const int tok0 = gw * 8;
    const int b = tok0 >> 9;
    const int cix = __ldg(corpus + b);
    const unsigned FULL = 0xffffffffu;

    float d[8];
    {
        float4 u0 = __ldg((const float4*)(g_ctr10 + cix * HID + lane * 8));
        float4 u1 = __ldg((const float4*)(g_ctr10 + cix * HID + lane * 8 + 4));
        d[0] = u0.x; d[1] = u0.y; d[2] = u0.z; d[3] = u0.w;
        d[4] = u1.x; d[5] = u1.y; d[6] = u1.z; d[7] = u1.w;
    }
    float w2[NTAGS][8];
#pragma unroll
    for (int t = 0; t < NTAGS; t++) {
        float4 u0 = __ldg((const float4*)(fc2_w + t * HID + lane * 8));
        float4 u1 = __ldg((const float4*)(fc2_w + t * HID + lane * 8 + 4));
        w2[t][0] = u0.x; w2[t][1] = u0.y; w2[t][2] = u0.z; w2[t][3] = u0.w;
        w2[t][4] = u1.x; w2[t][5] = u1.y; w2[t][6] = u1.z; w2[t][7] = u1.w;
    }
    const int tag = ((lane >> 4) & 1) * 4 + ((lane >> 3) & 1) * 2 + ((lane >> 2) & 1);
    const float fbt = __ldg(fc2_b + tag);

    // front-batch: 8 words -> 8 slots -> 8 Z-vectors
    int sl[8];
#pragma unroll
    for (int k = 0; k < 8; k++)
        sl[k] = __ldg(g_slot + __ldg(words + tok0 + k));
    uint4 zz[8];
#pragma unroll
    for (int k = 0; k < 8; k++)
        zz[k] = __ldg((const uint4*)(g_Zh + (long)sl[k] * (HID / 2) + lane * 4));

#pragma unroll
    for (int k = 0; k < 8; k++) {
        float h[8];
        h[0] = fmaxf(bf_lo(zz[k].x) + d[0], 0.f); h[1] = fmaxf(bf_hi(zz[k].x) + d[1], 0.f);
        h[2] = fmaxf(bf_lo(zz[k].y) + d[2], 0.f); h[3] = fmaxf(bf_hi(zz[k].y) + d[3], 0.f);
        h[4] = fmaxf(bf_lo(zz[k].z) + d[4], 0.f); h[5] = fmaxf(bf_hi(zz[k].z) + d[5], 0.f);
        h[6] = fmaxf(bf_lo(zz[k].w) + d[6], 0.f); h[7] = fmaxf(bf_hi(zz[k].w) + d[7], 0.f);

        float p[NTAGS];
#pragma unroll
        for (int t = 0; t < NTAGS; t++) {
            float s = 0.f;
#pragma unroll
            for (int q = 0; q < 8; q++) s = fmaf(h[q], w2[t][q], s);
            p[t] = s;
        }

        // tag-splitting butterfly: 9 shfls
#pragma unroll
        for (int i = 0; i < 4; i++) {
            float send = (lane & 16) ? p[i] : p[i + 4];
            float r = __shfl_xor_sync(FULL, send, 16);
            p[i] = ((lane & 16) ? p[i + 4] : p[i]) + r;
        }
#pragma unroll
        for (int i = 0; i < 2; i++) {
            float send = (lane & 8) ? p[i] : p[i + 2];
            float r = __shfl_xor_sync(FULL, send, 8);
            p[i] = ((lane & 8) ? p[i + 2] : p[i]) + r;
        }
        float v;
        {
            float send = (lane & 4) ? p[0] : p[1];
            float r = __shfl_xor_sync(FULL, send, 4);
            v = ((lane & 4) ? p[1] : p[0]) + r;
        }
        v += __shfl_xor_sync(FULL, v, 1);
        v += __shfl_xor_sync(FULL, v, 2);
        v += fbt;

        // softmax over tags (lanes differing in bits 2,3,4)
        float mx = v;
        mx = fmaxf(mx, __shfl_xor_sync(FULL, mx, 4));
        mx = fmaxf(mx, __shfl_xor_sync(FULL, mx, 8));
        mx = fmaxf(mx, __shfl_xor_sync(FULL, mx, 16));
        float sm = __expf(v - mx);
        sm += __shfl_xor_sync(FULL, sm, 4);
        sm += __shfl_xor_sync(FULL, sm, 8);
        sm += __shfl_xor_sync(FULL, sm, 16);
        float lse = mx + __logf(sm);

        if ((lane & 3) == 0)
            g_logits[(long)(tok0 + k) * NTAGS + tag] = v - lse;
    }
}

// ---------------------------------------------------------------------------
// crf_chunk: CLEN=16-step operator matrix per block. grid 2048, block 64.
// ---------------------------------------------------------------------------
__global__ __launch_bounds__(64) void crf_chunk(
    const int* __restrict__ words,
    const float* __restrict__ trans) {

    __shared__ float sL[CLEN * NTAGS];
    __shared__ int   sW[CLEN];

    const int b = blockIdx.x >> 5, chunk = blockIdx.x & 31;
    const int tid = threadIdx.x;
    const int j = tid & 7;
    const int lane = tid & 31, rowBase = lane & ~7;

    const float* L = g_logits + b * SEQ * NTAGS + chunk * CLEN * NTAGS;
    const int* wds = words + b * SEQ + chunk * CLEN;

    if (tid < 32) *(float4*)&sL[tid * 4] = *(const float4*)(L + tid * 4);
    if (tid < CLEN) sW[tid] = wds[tid];

    float tcol[8];
#pragma unroll
    for (int k = 0; k < 8; k++) tcol[k] = __ldg(trans + k * NTAGS + j);

    __syncthreads();

    float M = ((tid >> 3) == j) ? 0.f : -1e30f;
    const int skip0 = (chunk == 0);

#pragma unroll
    for (int s = 0; s < CLEN; s++) {
        float emit = sL[s * NTAGS + j];
        int live = (sW[s] != 0) & ((s > 0) | !skip0);
        float v[8];
#pragma unroll
        for (int k = 0; k < 8; k++)
            v[k] = __shfl_sync(0xffffffffu, M, rowBase + k) + tcol[k];
        float m01 = fmaxf(v[0], v[1]), m23 = fmaxf(v[2], v[3]);
        float m45 = fmaxf(v[4], v[5]), m67 = fmaxf(v[6], v[7]);
        float mx  = fmaxf(fmaxf(m01, m23), fmaxf(m45, m67));
        float s0 = __expf(v[0] - mx) + __expf(v[1] - mx);
        float s1 = __expf(v[2] - mx) + __expf(v[3] - mx);
        float s2 = __expf(v[4] - mx) + __expf(v[5] - mx);
        float s3 = __expf(v[6] - mx) + __expf(v[7] - mx);
        float nv = mx + __logf((s0 + s1) + (s2 + s3)) + emit;
        M = live ? nv : M;
    }
    g_crfM[blockIdx.x * 64 + tid] = M;
}

// ---------------------------------------------------------------------------
// crf_fin: combine 32 chunk matrices + norm + gold score. grid 64, block 512.
// ---------------------------------------------------------------------------
__global__ __launch_bounds__(512) void crf_fin(
    const int* __restrict__ words,
    const int* __restrict__ target,
    const float* __restrict__ trans,
    const float* __restrict__ start_s,
    const float* __restrict__ end_s,
    float* __restrict__ out) {

    __shared__ float sM[NCHUNK * 64];
    __shared__ float sRed[16];
    __shared__ int   sRedI[16];
    __shared__ float sNorm;

    const int b = blockIdx.x, tid = threadIdx.x;
    const int lane = tid & 31;
    const float* L = g_logits + b * SEQ * NTAGS;
    const int* wds = words + b * SEQ;
    const int* tg  = target + b * SEQ;

#pragma unroll
    for (int k = 0; k < 4; k++) sM[tid + k * 512] = g_crfM[b * (NCHUNK * 64) + tid + k * 512];
    __syncthreads();

    if (tid < 8) {
        float alpha = __ldg(L + tid) + __ldg(start_s + tid);
#pragma unroll
        for (int c = 0; c < NCHUNK; c++) {
            float v[8];
#pragma unroll
            for (int k = 0; k < 8; k++)
                v[k] = __shfl_sync(0xffu, alpha, k) + sM[c * 64 + k * 8 + tid];
            float m01 = fmaxf(v[0], v[1]), m23 = fmaxf(v[2], v[3]);
            float m45 = fmaxf(v[4], v[5]), m67 = fmaxf(v[6], v[7]);
            float mx  = fmaxf(fmaxf(m01, m23), fmaxf(m45, m67));
            float sm = __expf(v[0] - mx) + __expf(v[1] - mx) + __expf(v[2] - mx)
                     + __expf(v[3] - mx) + __expf(v[4] - mx) + __expf(v[5] - mx)
                     + __expf(v[6] - mx) + __expf(v[7] - mx);
            alpha = mx + __logf(sm);
        }
        float v = alpha + __ldg(end_s + tid);
        float mx = v;
        mx = fmaxf(mx, __shfl_xor_sync(0xffu, mx, 1));
        mx = fmaxf(mx, __shfl_xor_sync(0xffu, mx, 2));
        mx = fmaxf(mx, __shfl_xor_sync(0xffu, mx, 4));
        float sm = __expf(v - mx);
        sm += __shfl_xor_sync(0xffu, sm, 1);
        sm += __shfl_xor_sync(0xffu, sm, 2);
        sm += __shfl_xor_sync(0xffu, sm, 4);
        if (tid == 0) sNorm = mx + __logf(sm);
    }

    {
        const int s = tid;
        int m = (wds[s] != 0);
        int t = tg[s];
        float e  = m ? __ldg(L + s * NTAGS + t) : 0.f;
        float tr = (m && s > 0) ? __ldg(trans + tg[s - 1] * NTAGS + t) : 0.f;
        float val = e + tr;
        int cnt = m;
#pragma unroll
        for (int off = 16; off > 0; off >>= 1) {
            val += __shfl_down_sync(0xffffffffu, val, off);
            cnt += __shfl_down_sync(0xffffffffu, cnt, off);
        }
        if (lane == 0) { sRed[tid >> 5] = val; sRedI[tid >> 5] = cnt; }
    }
    __syncthreads();
    if (tid == 0) {
        float sum = 0.f; int c = 0;
#pragma unroll
        for (int w = 0; w < 16; w++) { sum += sRed[w]; c += sRedI[w]; }
        int last = c - 1;
        float score = sum + __ldg(start_s + tg[0]) + __ldg(end_s + tg[last]);
        out[b] = sNorm - score;
    }
}

// ---------------------------------------------------------------------------
extern "C" void kernel_launch(void* const* d_in, const int* in_sizes, int n_in,
                              void* d_out, int out_size) {
    const int*   words   = (const int*)  d_in[0];
    const int*   target  = (const int*)  d_in[1];
    const int*   corpus  = (const int*)  d_in[2];
    const float* embed_w = (const float*)d_in[3];
    const float* dom_w   = (const float*)d_in[4];
    const float* fc1_w   = (const float*)d_in[5];
    const float* fc1_b   = (const float*)d_in[6];
    const float* fc2_w   = (const float*)d_in[7];
    const float* fc2_b   = (const float*)d_in[8];
    const float* trans   = (const float*)d_in[9];
    const float* start_s = (const float*)d_in[10];
    const float* end_s   = (const float*)d_in[11];
    float* out = (float*)d_out;

    prep_all<<<190, 256>>>(fc1_w, dom_w, fc1_b);
    flag_compact<<<64, 512>>>(words);
    gemm_z<<<332, 256>>>(embed_w);
    tok_kernel<<<512, 256>>>(words, corpus, fc2_w, fc2_b);
    crf_chunk<<<BATCH * NCHUNK, 64>>>(words, trans);
    crf_fin<<<BATCH, 512>>>(words, target, trans, start_s, end_s, out);
}